// round 2
// baseline (speedup 1.0000x reference)
#include <cuda_runtime.h>
#include <math.h>

// Problem constants (fixed by the reference)
#define B     8192
#define C     2048
#define L     6
#define NRGB  4
#define HALF  (B/2)
#define M     (B + L)          // 8198
#define XOUT_ELEMS ((size_t)M * C)   // x_out is [(B+L), C]

// Scratch (device globals; no allocation allowed)
__device__ float g_scores[B];
__device__ float g_denom[L];
__device__ int   g_cnt[L];
__device__ float g_U[L * C];

// ---------------------------------------------------------------------------
// K0: zero the accumulators (re-run every launch; graph replays need this)
// ---------------------------------------------------------------------------
__global__ __launch_bounds__(256) void k_init() {
    int idx = blockIdx.x * 256 + threadIdx.x;
    if (idx < L * C) g_U[idx] = 0.0f;
    if (idx < L) { g_denom[idx] = 0.0f; g_cnt[idx] = 0; }
}

// ---------------------------------------------------------------------------
// K1: fused  x -> x_out copy  +  per-row attention score
//     score[r] = dot(x[r], att_w[cams[r]]) + att_b[cams[r]]
//     denom[cam] += score ; cnt[cam] += 1
// One block (256 thr) per row; float4 loads/stores.
// ---------------------------------------------------------------------------
__global__ __launch_bounds__(256) void k_score_copy(
    const float* __restrict__ x, const int* __restrict__ cams,
    const float* __restrict__ att_w, const float* __restrict__ att_b,
    float* __restrict__ out)
{
    int row = blockIdx.x;
    int t   = threadIdx.x;
    int cam = cams[row];

    const float4* xr = (const float4*)(x     + (size_t)row * C);
    const float4* wr = (const float4*)(att_w + (size_t)cam * C);
    float4*       orw = (float4*)(out + (size_t)row * C);

    float4 a0 = xr[t];
    float4 a1 = xr[t + 256];
    float4 w0 = wr[t];
    float4 w1 = wr[t + 256];

    // streaming store: don't pollute L2 (keep x resident for K2)
    __stcs(&orw[t],       a0);
    __stcs(&orw[t + 256], a1);

    float p = a0.x*w0.x + a0.y*w0.y + a0.z*w0.z + a0.w*w0.w
            + a1.x*w1.x + a1.y*w1.y + a1.z*w1.z + a1.w*w1.w;

    // block reduce (8 warps)
    #pragma unroll
    for (int o = 16; o; o >>= 1) p += __shfl_down_sync(0xffffffffu, p, o);
    __shared__ float sr[8];
    if ((t & 31) == 0) sr[t >> 5] = p;
    __syncthreads();
    if (t == 0) {
        float s = sr[0]+sr[1]+sr[2]+sr[3]+sr[4]+sr[5]+sr[6]+sr[7] + att_b[cam];
        g_scores[row] = s;
        atomicAdd(&g_denom[cam], s);
        atomicAdd(&g_cnt[cam], 1);
    }
}

// ---------------------------------------------------------------------------
// K2: cam_center[l][c] = sum_{r: cams[r]==l} x[r][c] * (score[r]/denom[l])
// Grid (8 col-tiles x 32 row-tiles), 256 rows per block.
// Thread t owns shared column slot t (bank-conflict-free: slot index ≡ t
// mod 32 within each cam plane), reduces 256 rows locally, then L global
// atomicAdds per thread.
// ---------------------------------------------------------------------------
#define ROWS_PER 256
__global__ __launch_bounds__(256) void k_center(
    const float* __restrict__ x, const int* __restrict__ cams)
{
    __shared__ float acc[L * 256];
    __shared__ float s_w[ROWS_PER];
    __shared__ int   s_cam[ROWS_PER];
    __shared__ float sinv[L];

    int t = threadIdx.x;
    if (t < L) sinv[t] = 1.0f / g_denom[t];   // unused cams -> inf, never read
    #pragma unroll
    for (int l = 0; l < L; l++) acc[l * 256 + t] = 0.0f;
    __syncthreads();

    int r0 = blockIdx.y * ROWS_PER;
    {
        int cm = cams[r0 + t];
        s_cam[t] = cm;
        s_w[t]   = g_scores[r0 + t] * sinv[cm];
    }
    __syncthreads();

    int col = blockIdx.x * 256 + t;
    const float* xp = x + (size_t)r0 * C + col;
    #pragma unroll 4
    for (int r = 0; r < ROWS_PER; r++) {
        int   cm = s_cam[r];
        float w  = s_w[r];
        acc[cm * 256 + t] += xp[(size_t)r * C] * w;
    }
    // each thread owns its slots exclusively -> no sync needed before readback
    #pragma unroll
    for (int l = 0; l < L; l++)
        atomicAdd(&g_U[l * C + col], acc[l * 256 + t]);
}

// ---------------------------------------------------------------------------
// K3: tail rows of x_out: cam present ? cam_center : running_mean
// ---------------------------------------------------------------------------
__global__ __launch_bounds__(256) void k_tail(
    const float* __restrict__ rmean, float* __restrict__ out)
{
    int idx = blockIdx.x * 256 + threadIdx.x;      // 0 .. L*C-1
    int l = idx >> 11;                              // /C (C=2048)
    float v = (g_cnt[l] > 0) ? g_U[idx] : rmean[idx];
    out[(size_t)B * C + idx] = v;
}

// ---------------------------------------------------------------------------
// K4: adjacency fill. Entirely data-independent: 5 constants + zeros.
//   sample rows: first-half -> (bb1 | 0 | tail{0,0,0,0,bc1,bc1})
//                second-half-> (0 | bb2 | tail{bc2 x4, 0,0})
//   cam rows:    IR  -> (bc1 | 0 | diag cc)   RGB -> (0 | bc2 | diag cc)
// One block per row, float2 stores (row stride 8198 f32 -> only 8B-aligned).
// ---------------------------------------------------------------------------
__global__ __launch_bounds__(256) void k_adj(
    float* __restrict__ adj,
    float bb1, float bb2, float cc, float bc1, float bc2)
{
    int i = blockIdx.x;           // 0 .. M-1
    int t = threadIdx.x;

    float lo, hi, tailv;
    if (i < B) {
        bool fh = (i < HALF);
        lo = fh ? bb1 : 0.0f;
        hi = fh ? 0.0f : bb2;
        bool ir = (t >= NRGB);
        tailv = (fh == ir) ? (fh ? bc1 : bc2) : 0.0f;
    } else {
        bool ir = (i - B) >= NRGB;
        lo = ir ? bc1 : 0.0f;
        hi = ir ? 0.0f : bc2;
        tailv = ((i - B) == t) ? cc : 0.0f;
    }

    float2* rp = (float2*)(adj + (size_t)i * M);
    #pragma unroll 4
    for (int v = t; v < 4096; v += 256) {           // j = 0 .. 8191
        float val = (v < 2048) ? lo : hi;
        __stcs(&rp[v], make_float2(val, val));
    }
    if (t < L)                                      // j = 8192 .. 8197
        adj[(size_t)i * M + B + t] = tailv;
}

// ---------------------------------------------------------------------------
// Inputs (metadata order): 0=x[B*C f32], 1=cams[B i32], 2=step, 3=modal,
//                          4=att_w[L*C f32], 5=att_b[L f32], 6=running_mean[L*C f32]
// Output: x_out [(B+L)*C] followed by adj [(B+L)^2], f32.
// ---------------------------------------------------------------------------
extern "C" void kernel_launch(void* const* d_in, const int* in_sizes, int n_in,
                              void* d_out, int out_size)
{
    const float* x     = (const float*)d_in[0];
    const int*   cams  = (const int*)  d_in[1];
    const float* att_w = (const float*)d_in[4];
    const float* att_b = (const float*)d_in[5];
    const float* rmean = (const float*)d_in[6];
    float* out = (float*)d_out;
    float* adj = out + XOUT_ELEMS;

    // degree constants (host-side, baked into the captured graph)
    double d1 = 1.0 / sqrt(4098.0);   // first-half sample rows
    double d2 = 1.0 / sqrt(4100.0);   // second-half sample rows
    double d3 = 1.0 / sqrt(4097.0);   // cam-node rows
    float bb1 = (float)(d1 * d1);
    float bb2 = (float)(d2 * d2);
    float cc  = (float)(d3 * d3);
    float bc1 = (float)(d1 * d3);
    float bc2 = (float)(d2 * d3);

    k_init<<<(L * C + 255) / 256, 256>>>();
    k_score_copy<<<B, 256>>>(x, cams, att_w, att_b, out);
    k_center<<<dim3(C / 256, B / ROWS_PER), 256>>>(x, cams);
    k_tail<<<(L * C + 255) / 256, 256>>>(rmean, out);
    k_adj<<<M, 256>>>(adj, bb1, bb2, cc, bc1, bc2);
}

// round 5
// speedup vs baseline: 1.0638x; 1.0638x over previous
#include <cuda_runtime.h>
#include <math.h>

// Problem constants (fixed by the reference)
#define B     8192
#define C     2048
#define L     6
#define NRGB  4
#define HALF  (B/2)
#define M     (B + L)          // 8198
#define XOUT_ELEMS ((size_t)M * C)

// adj row sharding across the three kernels
#define ADJ_A 5000
#define ADJ_B 3000
#define ADJ_C 198   // ADJ_A + ADJ_B + ADJ_C == M

// Scratch (device globals; no allocation allowed)
__device__ float g_scores[B];
__device__ float g_denom[L];
__device__ int   g_cnt[L];
__device__ float g_U[L * C];

// ---------------------------------------------------------------------------
// adj row writer: entirely data-independent (5 constants + zeros).
//   sample rows: first-half -> (bb1 | 0 | {0,0,0,0,bc1,bc1})
//                second-half-> (0 | bb2 | {bc2 x4, 0,0})
//   cam rows:    IR  -> (bc1 | 0 | diag cc)   RGB -> (0 | bc2 | diag cc)
// 256 threads, float2 streaming stores (row stride 8198 f32 = 8B-aligned).
// ---------------------------------------------------------------------------
__device__ __forceinline__ void adj_row(
    float* __restrict__ adj, int i, int t,
    float bb1, float bb2, float cc, float bc1, float bc2)
{
    float lo, hi, tailv;
    if (i < B) {
        bool fh = (i < HALF);
        lo = fh ? bb1 : 0.0f;
        hi = fh ? 0.0f : bb2;
        bool ir = (t >= NRGB);
        tailv = (fh == ir) ? (fh ? bc1 : bc2) : 0.0f;
    } else {
        bool ir = (i - B) >= NRGB;
        lo = ir ? bc1 : 0.0f;
        hi = ir ? 0.0f : bc2;
        tailv = ((i - B) == t) ? cc : 0.0f;
    }

    float2* rp = (float2*)(adj + (size_t)i * M);
    #pragma unroll 4
    for (int v = t; v < 4096; v += 256) {           // j = 0 .. 8191
        float val = (v < 2048) ? lo : hi;
        __stcs(&rp[v], make_float2(val, val));
    }
    if (t < L)                                      // j = 8192 .. 8197
        adj[(size_t)i * M + B + t] = tailv;
}

// ---------------------------------------------------------------------------
// K0: zero the accumulators (must precede A's atomics; tiny)
// ---------------------------------------------------------------------------
__global__ __launch_bounds__(256) void k_init() {
    int idx = blockIdx.x * 256 + threadIdx.x;
    if (idx < L * C) g_U[idx] = 0.0f;
    if (idx < L) { g_denom[idx] = 0.0f; g_cnt[idx] = 0; }
}

// ---------------------------------------------------------------------------
// Kernel A: blocks [0,B)  : fused x->x_out copy + attention score + denom
//           blocks [B,..) : adj rows 0 .. ADJ_A-1
// ---------------------------------------------------------------------------
__global__ __launch_bounds__(256) void k_A(
    const float* __restrict__ x, const int* __restrict__ cams,
    const float* __restrict__ att_w, const float* __restrict__ att_b,
    float* __restrict__ out, float* __restrict__ adj,
    float bb1, float bb2, float cc, float bc1, float bc2)
{
    int t = threadIdx.x;
    if (blockIdx.x >= B) {                      // adj shard
        adj_row(adj, blockIdx.x - B, t, bb1, bb2, cc, bc1, bc2);
        return;
    }

    int row = blockIdx.x;
    int cam = cams[row];

    const float4* xr = (const float4*)(x     + (size_t)row * C);
    const float4* wr = (const float4*)(att_w + (size_t)cam * C);
    float4*       ow = (float4*)(out + (size_t)row * C);

    float4 a0 = xr[t];
    float4 a1 = xr[t + 256];
    float4 w0 = wr[t];
    float4 w1 = wr[t + 256];

    // streaming store: keep x L2-resident for kernel B's reread
    __stcs(&ow[t],       a0);
    __stcs(&ow[t + 256], a1);

    float p = a0.x*w0.x + a0.y*w0.y + a0.z*w0.z + a0.w*w0.w
            + a1.x*w1.x + a1.y*w1.y + a1.z*w1.z + a1.w*w1.w;

    #pragma unroll
    for (int o = 16; o; o >>= 1) p += __shfl_down_sync(0xffffffffu, p, o);
    __shared__ float sr[8];
    if ((t & 31) == 0) sr[t >> 5] = p;
    __syncthreads();
    if (t == 0) {
        float s = sr[0]+sr[1]+sr[2]+sr[3]+sr[4]+sr[5]+sr[6]+sr[7] + att_b[cam];
        g_scores[row] = s;
        atomicAdd(&g_denom[cam], s);
        atomicAdd(&g_cnt[cam], 1);
    }
}

// ---------------------------------------------------------------------------
// Kernel B: blocks [0,256) : cam_center segment-sum (8 col-tiles x 32 row-tiles)
//           blocks [256,..): adj rows ADJ_A .. ADJ_A+ADJ_B-1
// ---------------------------------------------------------------------------
#define ROWS_PER 256
#define NCENTER  ((C / 256) * (B / ROWS_PER))   // 8 * 32 = 256
__global__ __launch_bounds__(256) void k_B(
    const float* __restrict__ x, const int* __restrict__ cams,
    float* __restrict__ adj,
    float bb1, float bb2, float cc, float bc1, float bc2)
{
    int t = threadIdx.x;
    if (blockIdx.x >= NCENTER) {                // adj shard
        adj_row(adj, ADJ_A + (blockIdx.x - NCENTER), t, bb1, bb2, cc, bc1, bc2);
        return;
    }

    __shared__ float acc[L * 256];
    __shared__ float s_w[ROWS_PER];
    __shared__ int   s_cam[ROWS_PER];
    __shared__ float sinv[L];

    int bx = blockIdx.x & 7;          // col tile (0..7)
    int by = blockIdx.x >> 3;         // row tile (0..31)

    if (t < L) sinv[t] = 1.0f / g_denom[t];   // absent cams -> inf, never read
    #pragma unroll
    for (int l = 0; l < L; l++) acc[l * 256 + t] = 0.0f;
    __syncthreads();

    int r0 = by * ROWS_PER;
    {
        int cm = cams[r0 + t];
        s_cam[t] = cm;
        s_w[t]   = g_scores[r0 + t] * sinv[cm];
    }
    __syncthreads();

    int col = bx * 256 + t;
    const float* xp = x + (size_t)r0 * C + col;
    #pragma unroll 4
    for (int r = 0; r < ROWS_PER; r++) {
        int   cm = s_cam[r];
        float w  = s_w[r];
        acc[cm * 256 + t] += xp[(size_t)r * C] * w;
    }
    // thread t owns its slots exclusively -> no sync before readback
    #pragma unroll
    for (int l = 0; l < L; l++)
        atomicAdd(&g_U[l * C + col], acc[l * 256 + t]);
}

// ---------------------------------------------------------------------------
// Kernel C: blocks [0,48)  : tail rows of x_out (present? center : running_mean)
//           blocks [48,..) : adj rows ADJ_A+ADJ_B .. M-1
// ---------------------------------------------------------------------------
#define NTAIL ((L * C + 255) / 256)   // 48
__global__ __launch_bounds__(256) void k_C(
    const float* __restrict__ rmean, float* __restrict__ out,
    float* __restrict__ adj,
    float bb1, float bb2, float cc, float bc1, float bc2)
{
    int t = threadIdx.x;
    if (blockIdx.x >= NTAIL) {                  // adj shard
        adj_row(adj, ADJ_A + ADJ_B + (blockIdx.x - NTAIL), t, bb1, bb2, cc, bc1, bc2);
        return;
    }
    int idx = blockIdx.x * 256 + t;             // 0 .. L*C-1
    int l = idx >> 11;                          // /C (C=2048)
    float v = (g_cnt[l] > 0) ? g_U[idx] : rmean[idx];
    out[(size_t)B * C + idx] = v;
}

// ---------------------------------------------------------------------------
// Inputs (metadata order): 0=x[B*C f32], 1=cams[B i32], 2=step, 3=modal,
//                          4=att_w[L*C f32], 5=att_b[L f32], 6=running_mean[L*C f32]
// Output: x_out [(B+L)*C] followed by adj [(B+L)^2], f32.
// ---------------------------------------------------------------------------
extern "C" void kernel_launch(void* const* d_in, const int* in_sizes, int n_in,
                              void* d_out, int out_size)
{
    const float* x     = (const float*)d_in[0];
    const int*   cams  = (const int*)  d_in[1];
    const float* att_w = (const float*)d_in[4];
    const float* att_b = (const float*)d_in[5];
    const float* rmean = (const float*)d_in[6];
    float* out = (float*)d_out;
    float* adj = out + XOUT_ELEMS;

    // degree constants (data-independent; baked into the captured graph)
    double d1 = 1.0 / sqrt(4098.0);   // first-half sample rows
    double d2 = 1.0 / sqrt(4100.0);   // second-half sample rows
    double d3 = 1.0 / sqrt(4097.0);   // cam-node rows
    float bb1 = (float)(d1 * d1);
    float bb2 = (float)(d2 * d2);
    float cc  = (float)(d3 * d3);
    float bc1 = (float)(d1 * d3);
    float bc2 = (float)(d2 * d3);

    k_init<<<(L * C + 255) / 256, 256>>>();
    k_A<<<B + ADJ_A, 256>>>(x, cams, att_w, att_b, out, adj,
                            bb1, bb2, cc, bc1, bc2);
    k_B<<<NCENTER + ADJ_B, 256>>>(x, cams, adj, bb1, bb2, cc, bc1, bc2);
    k_C<<<NTAIL + ADJ_C, 256>>>(rmean, out, adj, bb1, bb2, cc, bc1, bc2);
}